// round 12
// baseline (speedup 1.0000x reference)
#include <cuda_runtime.h>
#include <cuda_bf16.h>
#include <math.h>
#include <stdint.h>

// ---------------------------------------------------------------------------
// SemanticConsistencyLoss — R12: accum frozen at R11 (measured best);
// tail rebuilt as 2-stage parallel reduction:
//   stage A: grid (150 cls, 2 tensors x 4 quarters) -> g_part  (~4 us)
//   stage B: grid (150): combine partials + counts, d^2, tree, ticket->norm
// ---------------------------------------------------------------------------

#define NUM_CLASSES 150
#define CH        256
#define HCH       128
#define NPIX      (512 * 512)
#define CHUNKS    74
#define PPC       3584            // 74*3584 >= NPIX, multiple of 32
#define TPX       32
#define TPB       512
#define TSTRIDE   33
#define TILE_W    (HCH * TSTRIDE) // 4224 words per buffer

__device__ float g_psums[2][CHUNKS][NUM_CLASSES][CH];
__device__ float g_pcnts[2][CHUNKS][NUM_CLASSES];
__device__ float g_part[2][4][NUM_CLASSES][CH];
__device__ float g_csq[NUM_CLASSES];
__device__ unsigned int g_ticket = 0;

// smem floats: tile[2][4224] | lbl[3584] | cnt[152]
#define SM_LBL      (2 * TILE_W)
#define SM_CNT      (SM_LBL + PPC)
#define SMEM_FLOATS (SM_CNT + 152)
#define SMEM_BYTES  (SMEM_FLOATS * 4)   // ~48.7 KB -> occ 2

#define ACC_CASE(k)                                                        \
    case k: acc[k].x += v0; acc[k].y += v1; acc[k].z += v2; acc[k].w += v3; break;

__global__ void __launch_bounds__(TPB, 2)
accum_kernel(const float* __restrict__ src, const float* __restrict__ trg,
             const int* __restrict__ slab, const int* __restrict__ tlab) {
    extern __shared__ float smf[];
    float* tiles = smf;                 // [2][128][33]
    int*   lbl_s = (int*)(smf + SM_LBL);
    int*   cnt   = (int*)(smf + SM_CNT);

    const int chunk = blockIdx.x;
    const int tsel  = blockIdx.y;
    const int chalf = blockIdx.z;
    const float* __restrict__ F =
        (tsel ? trg : src) + (size_t)chalf * HCH * NPIX;
    const int*   __restrict__ L = tsel ? tlab : slab;

    const int tid  = threadIdx.x;
    const int wid  = tid >> 5;          // owns labels lab&15 == wid
    const int lane = tid & 31;

    if (tid < NUM_CLASSES) cnt[tid] = 0;
    __syncthreads();

    const int pbase  = chunk * PPC;
    const int psz    = min(PPC, NPIX - pbase);
    const int ntiles = psz / TPX;       // 112 (last chunk: 16)

    // ---- cache labels in smem + histogram (integer-exact) ----
    for (int i = tid; i < psz; i += TPB) {
        int l = L[pbase + i];
        lbl_s[i] = l;
        if (chalf == 0) atomicAdd(&cnt[l], 1);
    }
    __syncthreads();

    // ---- register accumulators: class 16k+wid, channels lane+{0,32,64,96} ----
    float4 acc[10];
#pragma unroll
    for (int k = 0; k < 10; ++k) acc[k] = make_float4(0.f, 0.f, 0.f, 0.f);

    // ---- register prefetch of tile 0 ----
    float4 r[2];
    int mylbl;
    {
#pragma unroll
        for (int i = 0; i < 2; ++i) {
            int q = tid + TPB * i;
            int ch = q >> 3, p4 = q & 7;
            r[i] = *(const float4*)(F + (size_t)ch * NPIX + pbase + p4 * 4);
        }
        mylbl = lbl_s[lane];
    }

    for (int t = 0; t < ntiles; ++t) {
        float* tb = tiles + (t & 1) * TILE_W;

        // ---- stage: bank-perfect scalar stores ----
#pragma unroll
        for (int i = 0; i < 2; ++i) {
            int q = tid + TPB * i;
            int ch = q >> 3, p4 = q & 7;
            float* d = tb + ch * TSTRIDE + p4 * 4;
            d[0] = r[i].x; d[1] = r[i].y; d[2] = r[i].z; d[3] = r[i].w;
        }
        const int lblcur = mylbl;
        __syncthreads();   // one barrier per tile (double buffer -> safe)

        // ---- prefetch next tile (label from smem: short latency) ----
        if (t + 1 < ntiles) {
            const int p0 = pbase + (t + 1) * TPX;
#pragma unroll
            for (int i = 0; i < 2; ++i) {
                int q = tid + TPB * i;
                int ch = q >> 3, p4 = q & 7;
                r[i] = *(const float4*)(F + (size_t)ch * NPIX + p0 + p4 * 4);
            }
            mylbl = lbl_s[(t + 1) * TPX + lane];
        }

        // ---- accumulate into registers: warp-uniform class switch ----
        unsigned m = __ballot_sync(0xffffffffu, (lblcur & 15) == wid);
        while (m) {
            const int j = __ffs(m) - 1;
            m &= m - 1;
            const int row = __shfl_sync(0xffffffffu, lblcur, j);
            const float* srcc = tb + lane * TSTRIDE + j;   // bank = lane+j
            const float v0 = srcc[0];
            const float v1 = srcc[32 * TSTRIDE];
            const float v2 = srcc[64 * TSTRIDE];
            const float v3 = srcc[96 * TSTRIDE];
            switch (row >> 4) {        // warp-uniform branch
                ACC_CASE(0) ACC_CASE(1) ACC_CASE(2) ACC_CASE(3) ACC_CASE(4)
                ACC_CASE(5) ACC_CASE(6) ACC_CASE(7) ACC_CASE(8) ACC_CASE(9)
            }
        }
    }
    __syncthreads();

    // ---- epilogue: registers -> partial scratch (coalesced per lane) ----
    const int nk = (wid < 6) ? 10 : 9;   // classes 16k+wid <= 149
#pragma unroll
    for (int k = 0; k < 10; ++k) {
        if (k < nk) {
            const int cls = 16 * k + wid;
            float* o = &g_psums[tsel][chunk][cls][chalf * HCH];
            o[lane]      = acc[k].x;
            o[lane + 32] = acc[k].y;
            o[lane + 64] = acc[k].z;
            o[lane + 96] = acc[k].w;
        }
    }
    if (chalf == 0 && tid < NUM_CLASSES)
        g_pcnts[tsel][chunk][tid] = (float)cnt[tid];
}

// ---- stage A: (class, tensor x quarter) partial chunk sums ----
__global__ void reduce_part() {
    const int cls  = blockIdx.x;
    const int part = blockIdx.y;          // 0..7
    const int tsel = part >> 2;
    const int qt   = part & 3;
    const int ch   = threadIdx.x;

    const int c0 = qt * 19;
    const int c1 = min(CHUNKS, c0 + 19);  // 19,19,19,17

    float s = 0.0f;
#pragma unroll 19
    for (int k = c0; k < c1; ++k)
        s += g_psums[tsel][k][cls][ch];
    g_part[tsel][qt][cls][ch] = s;
}

// ---- stage B: combine partials + counts, per-class d^2, ticket -> norm ----
__global__ void reduce_final(float* out) {
    const int cls = blockIdx.x;
    const int ch  = threadIdx.x;

    const float ss = g_part[0][0][cls][ch] + g_part[0][1][cls][ch]
                   + g_part[0][2][cls][ch] + g_part[0][3][cls][ch];
    const float st = g_part[1][0][cls][ch] + g_part[1][1][cls][ch]
                   + g_part[1][2][cls][ch] + g_part[1][3][cls][ch];

    // counts: 148 parallel loads, dual shared-tree (deterministic)
    __shared__ float c0s[128], c1s[128];
    {
        const int a = ch >> 7;            // 0: c0s, 1: c1s
        const int i = ch & 127;
        float v = (i < CHUNKS) ? g_pcnts[a][i][cls] : 0.0f;
        (a ? c1s : c0s)[i] = v;
    }
    __syncthreads();
#pragma unroll
    for (int s = 64; s > 0; s >>= 1) {
        const int a = ch >> 7;
        const int i = ch & 127;
        if (i < s) {
            float* arr = a ? c1s : c0s;
            arr[i] += arr[i + s];
        }
        __syncthreads();
    }
    const float cs  = c0s[0];
    const float ctn = c1s[0];

    const float d = ss / (cs + 1e-8f) - st / (ctn + 1e-8f);

    __shared__ float red[CH];
    __shared__ unsigned int is_last;
    red[ch] = d * d;
    __syncthreads();
#pragma unroll
    for (int s = CH / 2; s > 0; s >>= 1) {
        if (ch < s) red[ch] += red[ch + s];
        __syncthreads();
    }
    if (ch == 0) {
        g_csq[cls] = red[0];
        __threadfence();
        unsigned int t = atomicAdd(&g_ticket, 1u);
        is_last = (t == (unsigned)gridDim.x - 1u) ? 1u : 0u;
    }
    __syncthreads();

    if (is_last && ch < 32) {
        float s = 0.0f;
#pragma unroll
        for (int i = ch; i < NUM_CLASSES; i += 32)
            s += __ldcg(&g_csq[i]);
#pragma unroll
        for (int o = 16; o > 0; o >>= 1)
            s += __shfl_down_sync(0xffffffffu, s, o);
        if (ch == 0) {
            out[0] = sqrtf(s);
            g_ticket = 0;              // reset for next graph replay
        }
    }
}

extern "C" void kernel_launch(void* const* d_in, const int* in_sizes, int n_in,
                              void* d_out, int out_size) {
    const float* src = (const float*)d_in[0];   // src_fea  [1,256,512,512] f32
    const float* trg = (const float*)d_in[1];   // trg_fea
    const int*   sl  = (const int*)d_in[2];     // src_labels [1,512,512] i32
    const int*   tl  = (const int*)d_in[3];     // trg_pseudo_labels
    float* out = (float*)d_out;

    cudaFuncSetAttribute(accum_kernel,
                         cudaFuncAttributeMaxDynamicSharedMemorySize,
                         SMEM_BYTES);

    dim3 grid(CHUNKS, 2, 2);   // 296 CTAs = one wave at occ 2
    accum_kernel<<<grid, TPB, SMEM_BYTES>>>(src, trg, sl, tl);
    reduce_part<<<dim3(NUM_CLASSES, 8), CH>>>();
    reduce_final<<<NUM_CLASSES, CH>>>(out);
}

// round 13
// speedup vs baseline: 1.0499x; 1.0499x over previous
#include <cuda_runtime.h>
#include <cuda_bf16.h>
#include <math.h>
#include <stdint.h>

// ---------------------------------------------------------------------------
// SemanticConsistencyLoss — R13: accum frozen at R12 (measured best);
// tail = ONE kernel, grid 150 x block 1024:
//   thread (ch, part): 37-chunk partial sums (part = tensor x chunk-half),
//   smem combine -> centers diff -> d^2 tree -> ticket block -> norm.
// ---------------------------------------------------------------------------

#define NUM_CLASSES 150
#define CH        256
#define HCH       128
#define NPIX      (512 * 512)
#define CHUNKS    74
#define HCHUNK    37
#define PPC       3584            // 74*3584 >= NPIX, multiple of 32
#define TPX       32
#define TPB       512
#define TSTRIDE   33
#define TILE_W    (HCH * TSTRIDE) // 4224 words per buffer

__device__ float g_psums[2][CHUNKS][NUM_CLASSES][CH];
__device__ float g_pcnts[2][CHUNKS][NUM_CLASSES];
__device__ float g_csq[NUM_CLASSES];
__device__ unsigned int g_ticket = 0;

// smem floats: tile[2][4224] | lbl[3584] | cnt[152]
#define SM_LBL      (2 * TILE_W)
#define SM_CNT      (SM_LBL + PPC)
#define SMEM_FLOATS (SM_CNT + 152)
#define SMEM_BYTES  (SMEM_FLOATS * 4)   // ~48.7 KB -> occ 2

#define ACC_CASE(k)                                                        \
    case k: acc[k].x += v0; acc[k].y += v1; acc[k].z += v2; acc[k].w += v3; break;

__global__ void __launch_bounds__(TPB, 2)
accum_kernel(const float* __restrict__ src, const float* __restrict__ trg,
             const int* __restrict__ slab, const int* __restrict__ tlab) {
    extern __shared__ float smf[];
    float* tiles = smf;                 // [2][128][33]
    int*   lbl_s = (int*)(smf + SM_LBL);
    int*   cnt   = (int*)(smf + SM_CNT);

    const int chunk = blockIdx.x;
    const int tsel  = blockIdx.y;
    const int chalf = blockIdx.z;
    const float* __restrict__ F =
        (tsel ? trg : src) + (size_t)chalf * HCH * NPIX;
    const int*   __restrict__ L = tsel ? tlab : slab;

    const int tid  = threadIdx.x;
    const int wid  = tid >> 5;          // owns labels lab&15 == wid
    const int lane = tid & 31;

    if (tid < NUM_CLASSES) cnt[tid] = 0;
    __syncthreads();

    const int pbase  = chunk * PPC;
    const int psz    = min(PPC, NPIX - pbase);
    const int ntiles = psz / TPX;       // 112 (last chunk: 16)

    // ---- cache labels in smem + histogram (integer-exact) ----
    for (int i = tid; i < psz; i += TPB) {
        int l = L[pbase + i];
        lbl_s[i] = l;
        if (chalf == 0) atomicAdd(&cnt[l], 1);
    }
    __syncthreads();

    // ---- register accumulators: class 16k+wid, channels lane+{0,32,64,96} ----
    float4 acc[10];
#pragma unroll
    for (int k = 0; k < 10; ++k) acc[k] = make_float4(0.f, 0.f, 0.f, 0.f);

    // ---- register prefetch of tile 0 ----
    float4 r[2];
    int mylbl;
    {
#pragma unroll
        for (int i = 0; i < 2; ++i) {
            int q = tid + TPB * i;
            int ch = q >> 3, p4 = q & 7;
            r[i] = *(const float4*)(F + (size_t)ch * NPIX + pbase + p4 * 4);
        }
        mylbl = lbl_s[lane];
    }

    for (int t = 0; t < ntiles; ++t) {
        float* tb = tiles + (t & 1) * TILE_W;

        // ---- stage: bank-perfect scalar stores ----
#pragma unroll
        for (int i = 0; i < 2; ++i) {
            int q = tid + TPB * i;
            int ch = q >> 3, p4 = q & 7;
            float* d = tb + ch * TSTRIDE + p4 * 4;
            d[0] = r[i].x; d[1] = r[i].y; d[2] = r[i].z; d[3] = r[i].w;
        }
        const int lblcur = mylbl;
        __syncthreads();   // one barrier per tile (double buffer -> safe)

        // ---- prefetch next tile (label from smem: short latency) ----
        if (t + 1 < ntiles) {
            const int p0 = pbase + (t + 1) * TPX;
#pragma unroll
            for (int i = 0; i < 2; ++i) {
                int q = tid + TPB * i;
                int ch = q >> 3, p4 = q & 7;
                r[i] = *(const float4*)(F + (size_t)ch * NPIX + p0 + p4 * 4);
            }
            mylbl = lbl_s[(t + 1) * TPX + lane];
        }

        // ---- accumulate into registers: warp-uniform class switch ----
        unsigned m = __ballot_sync(0xffffffffu, (lblcur & 15) == wid);
        while (m) {
            const int j = __ffs(m) - 1;
            m &= m - 1;
            const int row = __shfl_sync(0xffffffffu, lblcur, j);
            const float* srcc = tb + lane * TSTRIDE + j;   // bank = lane+j
            const float v0 = srcc[0];
            const float v1 = srcc[32 * TSTRIDE];
            const float v2 = srcc[64 * TSTRIDE];
            const float v3 = srcc[96 * TSTRIDE];
            switch (row >> 4) {        // warp-uniform branch
                ACC_CASE(0) ACC_CASE(1) ACC_CASE(2) ACC_CASE(3) ACC_CASE(4)
                ACC_CASE(5) ACC_CASE(6) ACC_CASE(7) ACC_CASE(8) ACC_CASE(9)
            }
        }
    }
    __syncthreads();

    // ---- epilogue: registers -> partial scratch (coalesced per lane) ----
    const int nk = (wid < 6) ? 10 : 9;   // classes 16k+wid <= 149
#pragma unroll
    for (int k = 0; k < 10; ++k) {
        if (k < nk) {
            const int cls = 16 * k + wid;
            float* o = &g_psums[tsel][chunk][cls][chalf * HCH];
            o[lane]      = acc[k].x;
            o[lane + 32] = acc[k].y;
            o[lane + 64] = acc[k].z;
            o[lane + 96] = acc[k].w;
        }
    }
    if (chalf == 0 && tid < NUM_CLASSES)
        g_pcnts[tsel][chunk][tid] = (float)cnt[tid];
}

// ---- single tail kernel: grid 150, block 1024 ----
// part = tid>>8 (0..3): tsel = part&1, chunk-half = part>>1 (37 chunks each).
__global__ void __launch_bounds__(1024, 1)
reduce_kernel(float* out) {
    const int cls  = blockIdx.x;
    const int tid  = threadIdx.x;
    const int ch   = tid & 255;
    const int part = tid >> 8;          // 0..3
    const int tsel = part & 1;
    const int kh   = part >> 1;

    // 37 independent stride loads (high MLP), order-fixed sum
    float s = 0.0f;
    const int k0 = kh * HCHUNK;
#pragma unroll
    for (int k = 0; k < HCHUNK; ++k)
        s += g_psums[tsel][k0 + k][cls][ch];

    __shared__ float sp[4][CH];
    sp[part][ch] = s;

    // counts: 148 parallel loads, dual shared-tree (deterministic)
    __shared__ float c0s[128], c1s[128];
    if (tid < 256) {
        const int a = tid >> 7;         // 0: c0s, 1: c1s
        const int i = tid & 127;
        (a ? c1s : c0s)[i] = (i < CHUNKS) ? g_pcnts[a][i][cls] : 0.0f;
    }
    __syncthreads();
#pragma unroll
    for (int st = 64; st > 0; st >>= 1) {
        if (tid < 256) {
            const int a = tid >> 7;
            const int i = tid & 127;
            if (i < st) {
                float* arr = a ? c1s : c0s;
                arr[i] += arr[i + st];
            }
        }
        __syncthreads();
    }

    __shared__ float red[CH];
    if (tid < 256) {
        const float ssum = sp[0][ch] + sp[2][ch];   // tsel 0
        const float tsum = sp[1][ch] + sp[3][ch];   // tsel 1
        const float d = ssum / (c0s[0] + 1e-8f) - tsum / (c1s[0] + 1e-8f);
        red[ch] = d * d;
    }
    __syncthreads();
#pragma unroll
    for (int st = CH / 2; st > 0; st >>= 1) {
        if (tid < st) red[tid] += red[tid + st];
        __syncthreads();
    }

    __shared__ unsigned int is_last;
    if (tid == 0) {
        g_csq[cls] = red[0];
        __threadfence();
        unsigned int t = atomicAdd(&g_ticket, 1u);
        is_last = (t == (unsigned)gridDim.x - 1u) ? 1u : 0u;
    }
    __syncthreads();

    if (is_last && tid < 32) {
        float s2 = 0.0f;
#pragma unroll
        for (int i = tid; i < NUM_CLASSES; i += 32)
            s2 += __ldcg(&g_csq[i]);
#pragma unroll
        for (int o = 16; o > 0; o >>= 1)
            s2 += __shfl_down_sync(0xffffffffu, s2, o);
        if (tid == 0) {
            out[0] = sqrtf(s2);
            g_ticket = 0;              // reset for next graph replay
        }
    }
}

extern "C" void kernel_launch(void* const* d_in, const int* in_sizes, int n_in,
                              void* d_out, int out_size) {
    const float* src = (const float*)d_in[0];   // src_fea  [1,256,512,512] f32
    const float* trg = (const float*)d_in[1];   // trg_fea
    const int*   sl  = (const int*)d_in[2];     // src_labels [1,512,512] i32
    const int*   tl  = (const int*)d_in[3];     // trg_pseudo_labels
    float* out = (float*)d_out;

    cudaFuncSetAttribute(accum_kernel,
                         cudaFuncAttributeMaxDynamicSharedMemorySize,
                         SMEM_BYTES);

    dim3 grid(CHUNKS, 2, 2);   // 296 CTAs = one wave at occ 2
    accum_kernel<<<grid, TPB, SMEM_BYTES>>>(src, trg, sl, tl);
    reduce_kernel<<<NUM_CLASSES, 1024>>>(out);
}